// round 15
// baseline (speedup 1.0000x reference)
#include <cuda_runtime.h>

#define N_NODES 200000
#define E_PAD   4000000      // E + 7*N worst-case padded CSR
#define HD      32
#define BN_EPS  1e-5f
#define NB      740          // 148 SM x 5, all co-resident
#define NT      256
#define NGRP    (NB * 32)    // 8-lane groups

typedef unsigned long long u64;

// ---- packed f32x2 helpers (SASS FADD2/FFMA2/FMUL2; ptxas won't auto-fuse) ----
__device__ __forceinline__ void addf2(u64& a, u64 b) {
    asm("add.rn.f32x2 %0, %0, %1;" : "+l"(a) : "l"(b));
}
__device__ __forceinline__ void fmaf2(u64& d, u64 a, u64 b) {
    asm("fma.rn.f32x2 %0, %1, %2, %0;" : "+l"(d) : "l"(a), "l"(b));
}
__device__ __forceinline__ u64 fmaf2o(u64 a, u64 b, u64 c) {
    u64 d; asm("fma.rn.f32x2 %0, %1, %2, %3;" : "=l"(d) : "l"(a), "l"(b), "l"(c)); return d;
}
__device__ __forceinline__ u64 mulf2(u64 a, u64 b) {
    u64 d; asm("mul.rn.f32x2 %0, %1, %2;" : "=l"(d) : "l"(a), "l"(b)); return d;
}
__device__ __forceinline__ u64 pack2(float x, float y) {
    u64 d; asm("mov.b64 %0, {%1,%2};" : "=l"(d) : "f"(x), "f"(y)); return d;
}
__device__ __forceinline__ u64 bcast2(float x) {
    u64 d; asm("mov.b64 %0, {%1,%1};" : "=l"(d) : "f"(x)); return d;
}
__device__ __forceinline__ void unpack2(u64 v, float& x, float& y) {
    asm("mov.b64 {%0,%1}, %2;" : "=f"(x), "=f"(y) : "l"(v));
}

// ---- persistent scratch ----
__device__ unsigned g_tick;
__device__ int    g_deg[N_NODES];
__device__ int    g_off[N_NODES];
__device__ int    g_cur[N_NODES];
__device__ int    g_adj[E_PAD];
__device__ int    g_bsum[NB];
__device__ int    g_boff[NB];
__device__ float  g_norm[N_NODES];
__device__ float  g_xn[N_NODES + 1];        // +1: dummy row = 0
__device__ float  g_s[N_NODES];
// 3 node-feature buffers (reuse: A=U2 then Z3 ; B=Z2 ; C=U3)
__device__ float4 g_A[(N_NODES + 1) * 8];   // +1: dummy row = 0
__device__ float4 g_B[N_NODES * 8];
__device__ float4 g_C[(N_NODES + 1) * 8];   // +1: dummy row = 0
__device__ double g_stats[130];             // [0,1]=L1 ; [2..65]=L2 ; [66..129]=L3

// ---- device-wide barrier (monotonic ticket; graph-replay-safe) ----
__device__ __forceinline__ void gbar() {
    __threadfence();
    __syncthreads();
    if (threadIdx.x == 0) {
        unsigned nb = gridDim.x;
        unsigned t = atomicAdd(&g_tick, 1u) + 1u;
        unsigned need = ((t + nb - 1u) / nb) * nb;
        while (*((volatile unsigned*)&g_tick) < need) { __nanosleep(64); }
    }
    __syncthreads();
}

// ---- accumulate one 8-neighbor batch, packed f32x2 (16 ADD2 vs 32 FADD) ----
__device__ __forceinline__ void acc8p(const ulonglong2* __restrict__ U, int4 i0, int4 i1,
                                      int q, ulonglong2& acc) {
    ulonglong2 v0 = U[i0.x * 8 + q], v1 = U[i0.y * 8 + q];
    ulonglong2 v2 = U[i0.z * 8 + q], v3 = U[i0.w * 8 + q];
    ulonglong2 v4 = U[i1.x * 8 + q], v5 = U[i1.y * 8 + q];
    ulonglong2 v6 = U[i1.z * 8 + q], v7 = U[i1.w * 8 + q];
    addf2(v0.x, v1.x); addf2(v0.y, v1.y);
    addf2(v2.x, v3.x); addf2(v2.y, v3.y);
    addf2(v4.x, v5.x); addf2(v4.y, v5.y);
    addf2(v6.x, v7.x); addf2(v6.y, v7.y);
    addf2(v0.x, v2.x); addf2(v0.y, v2.y);
    addf2(v4.x, v6.x); addf2(v4.y, v6.y);
    addf2(v0.x, v4.x); addf2(v0.y, v4.y);
    addf2(acc.x, v0.x); addf2(acc.y, v0.y);
}

// ---- gather: 8-lane group per node; pipelined adj; packed math ----
__device__ __forceinline__ void gatherG(const float4* __restrict__ Uf, float4* __restrict__ Zf,
                                        const float* __restrict__ bvec,
                                        double* ss, double* sq, int n, double* shd) {
    const ulonglong2* U = (const ulonglong2*)Uf;
    ulonglong2* Z = (ulonglong2*)Zf;
    int tid = threadIdx.x, lane = tid & 31, q = tid & 7, wid = tid >> 5;
    int ggrp = blockIdx.x * 32 + (tid >> 3);
    float4 bf = ((const float4*)bvec)[q];
    u64 b01 = pack2(bf.x, bf.y), b23 = pack2(bf.z, bf.w);
    u64 sa01 = 0, sa23 = 0, sq01 = 0, sq23 = 0;   // f32x2 zero = 0ull

    for (int node = ggrp; node < n; node += NGRP) {
        int beg = g_off[node];
        int pd  = (g_deg[node] + 7) & ~7;
        const int4* ap = (const int4*)(g_adj + beg);
        ulonglong2 acc; acc.x = 0; acc.y = 0;
        if (pd) {
            int4 c0 = ap[0], c1 = ap[1]; ap += 2;          // prime
            for (int t = 8; t < pd; t += 8) {
                int4 n0 = ap[0], n1 = ap[1]; ap += 2;      // prefetch next batch
                acc8p(U, c0, c1, q, acc);                  // consume current
                c0 = n0; c1 = n1;
            }
            acc8p(U, c0, c1, q, acc);                      // drain
        }
        u64 nr2 = bcast2(g_norm[node]);
        ulonglong2 us = U[node * 8 + q];
        addf2(acc.x, us.x); addf2(acc.y, us.y);
        u64 z01 = fmaf2o(nr2, acc.x, b01);
        u64 z23 = fmaf2o(nr2, acc.y, b23);
        ulonglong2 zz; zz.x = z01; zz.y = z23;
        Z[node * 8 + q] = zz;
        addf2(sa01, z01); addf2(sa23, z23);
        fmaf2(sq01, z01, z01); fmaf2(sq23, z23, z23);
    }
    float4 a, a2;
    unpack2(sa01, a.x, a.y);  unpack2(sa23, a.z, a.w);
    unpack2(sq01, a2.x, a2.y); unpack2(sq23, a2.z, a2.w);
    // combine 4 groups of the warp (all lanes reconverged; full mask legal)
    #pragma unroll
    for (int o = 8; o <= 16; o <<= 1) {
        a.x += __shfl_xor_sync(0xffffffffu, a.x, o);   a.y += __shfl_xor_sync(0xffffffffu, a.y, o);
        a.z += __shfl_xor_sync(0xffffffffu, a.z, o);   a.w += __shfl_xor_sync(0xffffffffu, a.w, o);
        a2.x += __shfl_xor_sync(0xffffffffu, a2.x, o); a2.y += __shfl_xor_sync(0xffffffffu, a2.y, o);
        a2.z += __shfl_xor_sync(0xffffffffu, a2.z, o); a2.w += __shfl_xor_sync(0xffffffffu, a2.w, o);
    }
    __syncthreads();
    if (lane < 8) {
        int b = (wid * 8 + q) * 4;
        shd[b] = a.x; shd[b + 1] = a.y; shd[b + 2] = a.z; shd[b + 3] = a.w;
    }
    __syncthreads();
    if (tid < 32) {
        double s = 0.0;
        #pragma unroll
        for (int w = 0; w < 8; w++) s += shd[(w * 8 + (tid >> 2)) * 4 + (tid & 3)];
        atomicAdd(&ss[tid], s);
    }
    __syncthreads();
    if (lane < 8) {
        int b = (wid * 8 + q) * 4;
        shd[b] = a2.x; shd[b + 1] = a2.y; shd[b + 2] = a2.z; shd[b + 3] = a2.w;
    }
    __syncthreads();
    if (tid < 32) {
        double s = 0.0;
        #pragma unroll
        for (int w = 0; w < 8; w++) s += shd[(w * 8 + (tid >> 2)) * 4 + (tid & 3)];
        atomicAdd(&sq[tid], s);
    }
    __syncthreads();
}

// ---- dense: h = relu(bn(Zin)), Uout = (h @ Wn)*norm ; packed FFMA2 matvec ----
__device__ __forceinline__ void denseG(const float4* __restrict__ Zin, float4* __restrict__ Uout,
                                       const float* __restrict__ gv, const float* __restrict__ bev,
                                       const float* __restrict__ Wn,
                                       const double* ss, const double* sq, int n, float4* sW4) {
    for (int i = threadIdx.x; i < 256; i += NT) sW4[i] = ((const float4*)Wn)[i];
    __syncthreads();
    const ulonglong2* sWp = (const ulonglong2*)sW4;
    ulonglong2* Up = (ulonglong2*)Uout;
    int q = threadIdx.x & 7;
    unsigned gmask = 0xFFu << ((threadIdx.x & 31) & ~7);
    int ggrp = blockIdx.x * 32 + (threadIdx.x >> 3);
    float4 gl = ((const float4*)gv)[q], bl = ((const float4*)bev)[q];
    float4 mean, sd;
    {
        double inv = 1.0 / (double)n;
        double m0 = ss[4*q+0]*inv, m1 = ss[4*q+1]*inv, m2 = ss[4*q+2]*inv, m3 = ss[4*q+3]*inv;
        sd.x = rsqrtf((float)(sq[4*q+0]*inv - m0*m0) + BN_EPS);
        sd.y = rsqrtf((float)(sq[4*q+1]*inv - m1*m1) + BN_EPS);
        sd.z = rsqrtf((float)(sq[4*q+2]*inv - m2*m2) + BN_EPS);
        sd.w = rsqrtf((float)(sq[4*q+3]*inv - m3*m3) + BN_EPS);
        mean.x = (float)m0; mean.y = (float)m1; mean.z = (float)m2; mean.w = (float)m3;
    }
    for (int node = ggrp; node < n; node += NGRP) {
        float4 z = Zin[node * 8 + q];
        float4 h;
        h.x = fmaxf(gl.x * ((z.x - mean.x) * sd.x) + bl.x, 0.f);
        h.y = fmaxf(gl.y * ((z.y - mean.y) * sd.y) + bl.y, 0.f);
        h.z = fmaxf(gl.z * ((z.z - mean.z) * sd.z) + bl.z, 0.f);
        h.w = fmaxf(gl.w * ((z.w - mean.w) * sd.w) + bl.w, 0.f);
        u64 t01 = 0, t23 = 0;
        #pragma unroll
        for (int k = 0; k < 32; k++) {
            float hk = ((k & 3) == 0) ? h.x : ((k & 3) == 1) ? h.y : ((k & 3) == 2) ? h.z : h.w;
            hk = __shfl_sync(gmask, hk, k >> 2, 8);
            u64 hp = bcast2(hk);
            ulonglong2 w = sWp[k * 8 + q];
            fmaf2(t01, w.x, hp); fmaf2(t23, w.y, hp);
        }
        u64 nr2 = bcast2(g_norm[node]);
        ulonglong2 o; o.x = mulf2(t01, nr2); o.y = mulf2(t23, nr2);
        Up[node * 8 + q] = o;
    }
    __syncthreads();
}

__global__ void __launch_bounds__(NT, 5)
k_mega(const float* __restrict__ x, const int* __restrict__ src, const int* __restrict__ dst,
       const float* __restrict__ W1, const float* __restrict__ g1, const float* __restrict__ be1,
       const float* __restrict__ W2, const float* __restrict__ b2, const float* __restrict__ g2,
       const float* __restrict__ be2, const float* __restrict__ W3, const float* __restrict__ b3,
       const float* __restrict__ g3, const float* __restrict__ be3,
       const float* __restrict__ fcW, const float* __restrict__ fcb,
       float* __restrict__ out, int n, int E) {
    __shared__ float4 sW4[256];
    __shared__ double shd[NT];
    __shared__ int    shi[NT];

    int tid = threadIdx.x;
    int gt  = blockIdx.x * NT + tid;
    int lane = tid & 31, wid = tid >> 5;
    int q = tid & 7;
    unsigned gmask = 0xFFu << (lane & ~7);
    int ggrp = blockIdx.x * 32 + (tid >> 3);

    // ---- P0: zero deg/stats, zero dummy rows ----
    for (int i = gt; i < n; i += NB * NT) g_deg[i] = 0;
    if (gt < 130) g_stats[gt] = 0.0;
    if (gt >= 130 && gt < 138) {
        float4 zz = {0.f, 0.f, 0.f, 0.f};
        g_A[n * 8 + (gt - 130)] = zz;
        g_C[n * 8 + (gt - 130)] = zz;
    }
    if (gt == 138) g_xn[n] = 0.f;
    gbar();

    // ---- P1: degree histogram (edge reads streaming) ----
    for (int e = gt; e < E; e += NB * NT) atomicAdd(&g_deg[__ldcs(dst + e)], 1);
    gbar();

    // ---- P2a: per-block-range PADDED degree sums ----
    int C = (n + NB - 1) / NB;
    int base = blockIdx.x * C;
    int hi = min(n, base + C);
    {
        int s = 0;
        for (int i = base + tid; i < hi; i += NT) s += (g_deg[i] + 7) & ~7;
        for (int o = 16; o > 0; o >>= 1) s += __shfl_xor_sync(0xffffffffu, s, o);
        if (lane == 0) shi[wid] = s;
        __syncthreads();
        if (tid == 0) {
            int t = 0;
            #pragma unroll
            for (int k = 0; k < 8; k++) t += shi[k];
            g_bsum[blockIdx.x] = t;
        }
    }
    gbar();

    // ---- P2b: block 0 scans chunk sums ----
    if (blockIdx.x == 0) {
        int v0 = (3 * tid     < NB) ? g_bsum[3 * tid]     : 0;
        int v1 = (3 * tid + 1 < NB) ? g_bsum[3 * tid + 1] : 0;
        int v2 = (3 * tid + 2 < NB) ? g_bsum[3 * tid + 2] : 0;
        int s = v0 + v1 + v2;
        shi[tid] = s;
        __syncthreads();
        for (int o = 1; o < NT; o <<= 1) {
            int t = (tid >= o) ? shi[tid - o] : 0;
            __syncthreads();
            shi[tid] += t;
            __syncthreads();
        }
        int excl = shi[tid] - s;
        if (3 * tid     < NB) g_boff[3 * tid]     = excl;
        if (3 * tid + 1 < NB) g_boff[3 * tid + 1] = excl + v0;
        if (3 * tid + 2 < NB) g_boff[3 * tid + 2] = excl + v0 + v1;
    }
    gbar();

    // ---- P2c: per-node padded offsets + norm + xn + pad-fill with dummy ----
    {
        int i0 = base + tid * 2, i1 = i0 + 1;
        int d0 = (i0 < hi) ? g_deg[i0] : 0;
        int d1 = (i1 < hi) ? g_deg[i1] : 0;
        int p0 = (d0 + 7) & ~7, p1 = (d1 + 7) & ~7;
        int s = p0 + p1;
        shi[tid] = s;
        __syncthreads();
        for (int o = 1; o < NT; o <<= 1) {
            int t = (tid >= o) ? shi[tid - o] : 0;
            __syncthreads();
            shi[tid] += t;
            __syncthreads();
        }
        int run = g_boff[blockIdx.x] + shi[tid] - s;
        if (i0 < hi) {
            g_off[i0] = run; g_cur[i0] = run;
            float nr = rsqrtf((float)d0 + 1.0f);
            g_norm[i0] = nr; g_xn[i0] = x[i0] * nr;
            for (int w = d0; w < p0; w++) g_adj[run + w] = n;
        }
        if (i1 < hi) {
            int r1 = run + p0;
            g_off[i1] = r1; g_cur[i1] = r1;
            float nr = rsqrtf((float)d1 + 1.0f);
            g_norm[i1] = nr; g_xn[i1] = x[i1] * nr;
            for (int w = d1; w < p1; w++) g_adj[r1 + w] = n;
        }
    }
    gbar();

    // ---- P3: CSR fill (edge reads streaming) ----
    for (int e = gt; e < E; e += NB * NT) {
        int d = __ldcs(dst + e);
        int s = __ldcs(src + e);
        int pos = atomicAdd(&g_cur[d], 1);
        g_adj[pos] = s;
    }
    gbar();

    // ---- P4: layer-1 scalar gather (8-lane groups) + stats ----
    {
        float a = 0.f, a2 = 0.f;
        for (int node = ggrp; node < n; node += NGRP) {
            int beg = g_off[node];
            int pd = (g_deg[node] + 7) & ~7;
            float acc = 0.f;
            for (int j0 = 0; j0 < pd; j0 += 8) acc += g_xn[g_adj[beg + j0 + q]];
            acc += __shfl_xor_sync(gmask, acc, 4, 8);
            acc += __shfl_xor_sync(gmask, acc, 2, 8);
            acc += __shfl_xor_sync(gmask, acc, 1, 8);
            if (q == 0) {
                float nr = g_norm[node];
                float sv = nr * acc + x[node] * nr * nr;
                g_s[node] = sv;
                a += sv; a2 += sv * sv;
            }
        }
        a  += __shfl_xor_sync(0xffffffffu, a, 8);  a  += __shfl_xor_sync(0xffffffffu, a, 16);
        a2 += __shfl_xor_sync(0xffffffffu, a2, 8); a2 += __shfl_xor_sync(0xffffffffu, a2, 16);
        __syncthreads();
        if (lane == 0) { shd[wid] = (double)a; shd[8 + wid] = (double)a2; }
        __syncthreads();
        if (tid == 0) {
            double s1 = 0.0, s2 = 0.0;
            #pragma unroll
            for (int k = 0; k < 8; k++) { s1 += shd[k]; s2 += shd[8 + k]; }
            atomicAdd(&g_stats[0], s1); atomicAdd(&g_stats[1], s2);
        }
        __syncthreads();
    }
    gbar();

    // ---- P5: layer-1 dense -> A (=U2) (packed FFMA2 matvec) ----
    {
        for (int i = tid; i < 256; i += NT) sW4[i] = ((const float4*)W2)[i];
        __syncthreads();
        const ulonglong2* sWp = (const ulonglong2*)sW4;
        ulonglong2* Ap = (ulonglong2*)g_A;
        double inv = 1.0 / (double)n;
        double mu = g_stats[0] * inv;
        double vr = g_stats[1] * inv - mu * mu;
        float vrf = (float)vr, meanf = (float)mu;
        float4 w4 = ((const float4*)W1)[q];
        float4 gg = ((const float4*)g1)[q], bb = ((const float4*)be1)[q];
        float4 al;
        al.x = gg.x * w4.x * rsqrtf(vrf * w4.x * w4.x + BN_EPS);
        al.y = gg.y * w4.y * rsqrtf(vrf * w4.y * w4.y + BN_EPS);
        al.z = gg.z * w4.z * rsqrtf(vrf * w4.z * w4.z + BN_EPS);
        al.w = gg.w * w4.w * rsqrtf(vrf * w4.w * w4.w + BN_EPS);
        for (int node = ggrp; node < n; node += NGRP) {
            float sv = g_s[node];
            float4 h;
            h.x = fmaxf(al.x * (sv - meanf) + bb.x, 0.f);
            h.y = fmaxf(al.y * (sv - meanf) + bb.y, 0.f);
            h.z = fmaxf(al.z * (sv - meanf) + bb.z, 0.f);
            h.w = fmaxf(al.w * (sv - meanf) + bb.w, 0.f);
            u64 t01 = 0, t23 = 0;
            #pragma unroll
            for (int k = 0; k < 32; k++) {
                float hk = ((k & 3) == 0) ? h.x : ((k & 3) == 1) ? h.y : ((k & 3) == 2) ? h.z : h.w;
                hk = __shfl_sync(gmask, hk, k >> 2, 8);
                u64 hp = bcast2(hk);
                ulonglong2 w = sWp[k * 8 + q];
                fmaf2(t01, w.x, hp); fmaf2(t23, w.y, hp);
            }
            u64 nr2 = bcast2(g_norm[node]);
            ulonglong2 o; o.x = mulf2(t01, nr2); o.y = mulf2(t23, nr2);
            Ap[node * 8 + q] = o;
        }
        __syncthreads();
    }
    gbar();

    // ---- P6: layer-2 gather: A(U2) -> B(Z2) ----
    gatherG(g_A, g_B, b2, &g_stats[2], &g_stats[34], n, shd);
    gbar();

    // ---- P7: layer-2 dense: B(Z2) -> C(U3) ----
    denseG(g_B, g_C, g2, be2, W3, &g_stats[2], &g_stats[34], n, sW4);
    gbar();

    // ---- P8: layer-3 gather: C(U3) -> A(Z3; U2 storage dead) ----
    gatherG(g_C, g_A, b3, &g_stats[66], &g_stats[98], n, shd);
    gbar();

    // ---- P9: output from A(Z3) (4 nodes/warp) ----
    {
        const double* ss = &g_stats[66];
        const double* sq = &g_stats[98];
        double inv = 1.0 / (double)n;
        float4 gl = ((const float4*)g3)[q], bl = ((const float4*)be3)[q];
        float4 fw = ((const float4*)fcW)[q];
        float fb = fcb[0];
        float4 mean, sd;
        double m0 = ss[4*q+0]*inv, m1 = ss[4*q+1]*inv, m2 = ss[4*q+2]*inv, m3 = ss[4*q+3]*inv;
        sd.x = rsqrtf((float)(sq[4*q+0]*inv - m0*m0) + BN_EPS);
        sd.y = rsqrtf((float)(sq[4*q+1]*inv - m1*m1) + BN_EPS);
        sd.z = rsqrtf((float)(sq[4*q+2]*inv - m2*m2) + BN_EPS);
        sd.w = rsqrtf((float)(sq[4*q+3]*inv - m3*m3) + BN_EPS);
        mean.x = (float)m0; mean.y = (float)m1; mean.z = (float)m2; mean.w = (float)m3;
        for (int node = ggrp; node < n; node += NGRP) {
            float4 z = g_A[node * 8 + q];
            float4 h;
            h.x = fmaxf(gl.x * ((z.x - mean.x) * sd.x) + bl.x, 0.f);
            h.y = fmaxf(gl.y * ((z.y - mean.y) * sd.y) + bl.y, 0.f);
            h.z = fmaxf(gl.z * ((z.z - mean.z) * sd.z) + bl.z, 0.f);
            h.w = fmaxf(gl.w * ((z.w - mean.w) * sd.w) + bl.w, 0.f);
            float v = h.x * fw.x + h.y * fw.y + h.z * fw.z + h.w * fw.w;
            v += __shfl_xor_sync(gmask, v, 4, 8);
            v += __shfl_xor_sync(gmask, v, 2, 8);
            v += __shfl_xor_sync(gmask, v, 1, 8);
            if (q == 0) out[node] = v + fb;
        }
    }
}

extern "C" void kernel_launch(void* const* d_in, const int* in_sizes, int n_in,
                              void* d_out, int out_size) {
    const float* x   = (const float*)d_in[0];
    const int*   ei  = (const int*)d_in[1];     // int32 edge_index
    const float* W1  = (const float*)d_in[3];
    const float* g1  = (const float*)d_in[5];
    const float* be1 = (const float*)d_in[6];
    const float* W2  = (const float*)d_in[7];
    const float* b2  = (const float*)d_in[8];
    const float* g2  = (const float*)d_in[9];
    const float* be2 = (const float*)d_in[10];
    const float* W3  = (const float*)d_in[11];
    const float* b3  = (const float*)d_in[12];
    const float* g3  = (const float*)d_in[13];
    const float* be3 = (const float*)d_in[14];
    const float* fcW = (const float*)d_in[15];
    const float* fcb = (const float*)d_in[16];
    float* out = (float*)d_out;

    int n = in_sizes[0];
    int E = in_sizes[1] / 2;
    const int* src = ei;
    const int* dst = ei + E;

    k_mega<<<NB, NT>>>(x, src, dst, W1, g1, be1, W2, b2, g2, be2,
                       W3, b3, g3, be3, fcW, fcb, out, n, E);
}

// round 16
// speedup vs baseline: 1.0605x; 1.0605x over previous
#include <cuda_runtime.h>
#include <cuda_fp16.h>

#define N_NODES 200000
#define E_PAD   4000000      // E + 7*N worst-case padded CSR
#define HD      32
#define BN_EPS  1e-5f
#define NB      740          // 148 SM x 5, all co-resident
#define NT      256
#define NGRP    (NB * 32)    // 8-lane groups

// ---- persistent scratch ----
__device__ unsigned g_tick;
__device__ int    g_deg[N_NODES];
__device__ int    g_off[N_NODES];
__device__ int    g_cur[N_NODES];
__device__ int    g_adj[E_PAD];
__device__ int    g_bsum[NB];
__device__ int    g_boff[NB];
__device__ float  g_norm[N_NODES];
__device__ float  g_xn[N_NODES + 1];        // +1: dummy row = 0
__device__ float  g_s[N_NODES];
__device__ uint2  g_U2h[(N_NODES + 1) * 8]; // fp16 messages [N,32], 64B/row (+dummy)
__device__ uint2  g_U3h[(N_NODES + 1) * 8];
__device__ float4 g_Z[N_NODES * 8];         // fp32 pre-BN activations (Z2 then Z3)
__device__ double g_stats[130];             // [0,1]=L1 ; [2..65]=L2 ; [66..129]=L3

// ---- fp16 pack/unpack helpers ----
__device__ __forceinline__ void cvtAcc(uint2 v, float4& acc) {
    __half2 h01 = *reinterpret_cast<__half2*>(&v.x);
    __half2 h23 = *reinterpret_cast<__half2*>(&v.y);
    float2 f01 = __half22float2(h01);
    float2 f23 = __half22float2(h23);
    acc.x += f01.x; acc.y += f01.y; acc.z += f23.x; acc.w += f23.y;
}
__device__ __forceinline__ uint2 toH(float4 o) {
    __half2 a = __float22half2_rn(make_float2(o.x, o.y));
    __half2 b = __float22half2_rn(make_float2(o.z, o.w));
    uint2 r;
    r.x = *reinterpret_cast<unsigned*>(&a);
    r.y = *reinterpret_cast<unsigned*>(&b);
    return r;
}

// ---- device-wide barrier (monotonic ticket; graph-replay-safe) ----
__device__ __forceinline__ void gbar() {
    __threadfence();
    __syncthreads();
    if (threadIdx.x == 0) {
        unsigned nb = gridDim.x;
        unsigned t = atomicAdd(&g_tick, 1u) + 1u;
        unsigned need = ((t + nb - 1u) / nb) * nb;
        while (*((volatile unsigned*)&g_tick) < need) { __nanosleep(64); }
    }
    __syncthreads();
}

// ---- gather: 8-lane group per node; fp16 rows; 4-neighbor lookahead ----
__device__ __forceinline__ void gatherH(const uint2* __restrict__ U, float4* __restrict__ Z,
                                        const float* __restrict__ bvec,
                                        double* ss, double* sq, int n, double* shd) {
    int tid = threadIdx.x, lane = tid & 31, q = tid & 7, wid = tid >> 5;
    int ggrp = blockIdx.x * 32 + (tid >> 3);
    float4 b4 = ((const float4*)bvec)[q];
    float4 a  = {0.f, 0.f, 0.f, 0.f};
    float4 a2 = {0.f, 0.f, 0.f, 0.f};

    for (int node = ggrp; node < n; node += NGRP) {
        int beg = g_off[node];
        int pd  = (g_deg[node] + 7) & ~7;
        const int4* ap = (const int4*)(g_adj + beg);
        float4 acc = {0.f, 0.f, 0.f, 0.f};
        if (pd) {
            int nb4 = pd >> 2;                 // 4-neighbor steps (even count)
            int4 c = ap[0];
            uint2 v0 = U[c.x * 8 + q], v1 = U[c.y * 8 + q];
            uint2 v2 = U[c.z * 8 + q], v3 = U[c.w * 8 + q];
            for (int t = 1; t < nb4; t++) {
                int4 nx = ap[t];
                uint2 w0 = U[nx.x * 8 + q], w1 = U[nx.y * 8 + q];
                uint2 w2 = U[nx.z * 8 + q], w3 = U[nx.w * 8 + q];
                cvtAcc(v0, acc); cvtAcc(v1, acc); cvtAcc(v2, acc); cvtAcc(v3, acc);
                v0 = w0; v1 = w1; v2 = w2; v3 = w3;
            }
            cvtAcc(v0, acc); cvtAcc(v1, acc); cvtAcc(v2, acc); cvtAcc(v3, acc);
        }
        cvtAcc(U[node * 8 + q], acc);          // self term
        float nr = g_norm[node];
        float4 z;
        z.x = nr * acc.x + b4.x;
        z.y = nr * acc.y + b4.y;
        z.z = nr * acc.z + b4.z;
        z.w = nr * acc.w + b4.w;
        Z[node * 8 + q] = z;
        a.x += z.x; a.y += z.y; a.z += z.z; a.w += z.w;
        a2.x += z.x * z.x; a2.y += z.y * z.y; a2.z += z.z * z.z; a2.w += z.w * z.w;
    }
    // combine 4 groups of the warp (all lanes reconverged; full mask legal)
    #pragma unroll
    for (int o = 8; o <= 16; o <<= 1) {
        a.x += __shfl_xor_sync(0xffffffffu, a.x, o);   a.y += __shfl_xor_sync(0xffffffffu, a.y, o);
        a.z += __shfl_xor_sync(0xffffffffu, a.z, o);   a.w += __shfl_xor_sync(0xffffffffu, a.w, o);
        a2.x += __shfl_xor_sync(0xffffffffu, a2.x, o); a2.y += __shfl_xor_sync(0xffffffffu, a2.y, o);
        a2.z += __shfl_xor_sync(0xffffffffu, a2.z, o); a2.w += __shfl_xor_sync(0xffffffffu, a2.w, o);
    }
    __syncthreads();
    if (lane < 8) {
        int b = (wid * 8 + q) * 4;
        shd[b] = a.x; shd[b + 1] = a.y; shd[b + 2] = a.z; shd[b + 3] = a.w;
    }
    __syncthreads();
    if (tid < 32) {
        double s = 0.0;
        #pragma unroll
        for (int w = 0; w < 8; w++) s += shd[(w * 8 + (tid >> 2)) * 4 + (tid & 3)];
        atomicAdd(&ss[tid], s);
    }
    __syncthreads();
    if (lane < 8) {
        int b = (wid * 8 + q) * 4;
        shd[b] = a2.x; shd[b + 1] = a2.y; shd[b + 2] = a2.z; shd[b + 3] = a2.w;
    }
    __syncthreads();
    if (tid < 32) {
        double s = 0.0;
        #pragma unroll
        for (int w = 0; w < 8; w++) s += shd[(w * 8 + (tid >> 2)) * 4 + (tid & 3)];
        atomicAdd(&sq[tid], s);
    }
    __syncthreads();
}

// ---- dense: h = relu(bn(Zin)), Uout(fp16) = (h @ Wn)*norm ; 4 nodes/warp ----
__device__ __forceinline__ void denseH(const float4* __restrict__ Zin, uint2* __restrict__ Uout,
                                       const float* __restrict__ gv, const float* __restrict__ bev,
                                       const float* __restrict__ Wn,
                                       const double* ss, const double* sq, int n, float4* sW4) {
    for (int i = threadIdx.x; i < 256; i += NT) sW4[i] = ((const float4*)Wn)[i];
    __syncthreads();
    int q = threadIdx.x & 7;
    unsigned gmask = 0xFFu << ((threadIdx.x & 31) & ~7);
    int ggrp = blockIdx.x * 32 + (threadIdx.x >> 3);
    float4 gl = ((const float4*)gv)[q], bl = ((const float4*)bev)[q];
    float4 mean, sd;
    {
        double inv = 1.0 / (double)n;
        double m0 = ss[4*q+0]*inv, m1 = ss[4*q+1]*inv, m2 = ss[4*q+2]*inv, m3 = ss[4*q+3]*inv;
        sd.x = rsqrtf((float)(sq[4*q+0]*inv - m0*m0) + BN_EPS);
        sd.y = rsqrtf((float)(sq[4*q+1]*inv - m1*m1) + BN_EPS);
        sd.z = rsqrtf((float)(sq[4*q+2]*inv - m2*m2) + BN_EPS);
        sd.w = rsqrtf((float)(sq[4*q+3]*inv - m3*m3) + BN_EPS);
        mean.x = (float)m0; mean.y = (float)m1; mean.z = (float)m2; mean.w = (float)m3;
    }
    for (int node = ggrp; node < n; node += NGRP) {
        float4 z = Zin[node * 8 + q];
        float4 h;
        h.x = fmaxf(gl.x * ((z.x - mean.x) * sd.x) + bl.x, 0.f);
        h.y = fmaxf(gl.y * ((z.y - mean.y) * sd.y) + bl.y, 0.f);
        h.z = fmaxf(gl.z * ((z.z - mean.z) * sd.z) + bl.z, 0.f);
        h.w = fmaxf(gl.w * ((z.w - mean.w) * sd.w) + bl.w, 0.f);
        float4 t = {0.f, 0.f, 0.f, 0.f};
        #pragma unroll
        for (int k = 0; k < 32; k++) {
            float hk = ((k & 3) == 0) ? h.x : ((k & 3) == 1) ? h.y : ((k & 3) == 2) ? h.z : h.w;
            hk = __shfl_sync(gmask, hk, k >> 2, 8);
            float4 w = sW4[k * 8 + q];
            t.x += hk * w.x; t.y += hk * w.y; t.z += hk * w.z; t.w += hk * w.w;
        }
        float nr = g_norm[node];
        float4 o; o.x = t.x * nr; o.y = t.y * nr; o.z = t.z * nr; o.w = t.w * nr;
        Uout[node * 8 + q] = toH(o);
    }
    __syncthreads();
}

__global__ void __launch_bounds__(NT, 5)
k_mega(const float* __restrict__ x, const int* __restrict__ src, const int* __restrict__ dst,
       const float* __restrict__ W1, const float* __restrict__ g1, const float* __restrict__ be1,
       const float* __restrict__ W2, const float* __restrict__ b2, const float* __restrict__ g2,
       const float* __restrict__ be2, const float* __restrict__ W3, const float* __restrict__ b3,
       const float* __restrict__ g3, const float* __restrict__ be3,
       const float* __restrict__ fcW, const float* __restrict__ fcb,
       float* __restrict__ out, int n, int E) {
    __shared__ float4 sW4[256];
    __shared__ double shd[NT];
    __shared__ int    shi[NT];

    int tid = threadIdx.x;
    int gt  = blockIdx.x * NT + tid;
    int lane = tid & 31, wid = tid >> 5;
    int q = tid & 7;
    unsigned gmask = 0xFFu << (lane & ~7);
    int ggrp = blockIdx.x * 32 + (tid >> 3);

    // ---- P0: zero deg/stats, zero dummy rows ----
    for (int i = gt; i < n; i += NB * NT) g_deg[i] = 0;
    if (gt < 130) g_stats[gt] = 0.0;
    if (gt >= 130 && gt < 138) {
        uint2 zz = {0u, 0u};
        g_U2h[n * 8 + (gt - 130)] = zz;
        g_U3h[n * 8 + (gt - 130)] = zz;
    }
    if (gt == 138) g_xn[n] = 0.f;
    gbar();

    // ---- P1: degree histogram (edge reads streaming) ----
    for (int e = gt; e < E; e += NB * NT) atomicAdd(&g_deg[__ldcs(dst + e)], 1);
    gbar();

    // ---- P2a: per-block-range PADDED degree sums ----
    int C = (n + NB - 1) / NB;
    int base = blockIdx.x * C;
    int hi = min(n, base + C);
    {
        int s = 0;
        for (int i = base + tid; i < hi; i += NT) s += (g_deg[i] + 7) & ~7;
        for (int o = 16; o > 0; o >>= 1) s += __shfl_xor_sync(0xffffffffu, s, o);
        if (lane == 0) shi[wid] = s;
        __syncthreads();
        if (tid == 0) {
            int t = 0;
            #pragma unroll
            for (int k = 0; k < 8; k++) t += shi[k];
            g_bsum[blockIdx.x] = t;
        }
    }
    gbar();

    // ---- P2b: block 0 scans chunk sums ----
    if (blockIdx.x == 0) {
        int v0 = (3 * tid     < NB) ? g_bsum[3 * tid]     : 0;
        int v1 = (3 * tid + 1 < NB) ? g_bsum[3 * tid + 1] : 0;
        int v2 = (3 * tid + 2 < NB) ? g_bsum[3 * tid + 2] : 0;
        int s = v0 + v1 + v2;
        shi[tid] = s;
        __syncthreads();
        for (int o = 1; o < NT; o <<= 1) {
            int t = (tid >= o) ? shi[tid - o] : 0;
            __syncthreads();
            shi[tid] += t;
            __syncthreads();
        }
        int excl = shi[tid] - s;
        if (3 * tid     < NB) g_boff[3 * tid]     = excl;
        if (3 * tid + 1 < NB) g_boff[3 * tid + 1] = excl + v0;
        if (3 * tid + 2 < NB) g_boff[3 * tid + 2] = excl + v0 + v1;
    }
    gbar();

    // ---- P2c: per-node padded offsets + norm + xn + pad-fill with dummy ----
    {
        int i0 = base + tid * 2, i1 = i0 + 1;
        int d0 = (i0 < hi) ? g_deg[i0] : 0;
        int d1 = (i1 < hi) ? g_deg[i1] : 0;
        int p0 = (d0 + 7) & ~7, p1 = (d1 + 7) & ~7;
        int s = p0 + p1;
        shi[tid] = s;
        __syncthreads();
        for (int o = 1; o < NT; o <<= 1) {
            int t = (tid >= o) ? shi[tid - o] : 0;
            __syncthreads();
            shi[tid] += t;
            __syncthreads();
        }
        int run = g_boff[blockIdx.x] + shi[tid] - s;
        if (i0 < hi) {
            g_off[i0] = run; g_cur[i0] = run;
            float nr = rsqrtf((float)d0 + 1.0f);
            g_norm[i0] = nr; g_xn[i0] = x[i0] * nr;
            for (int w = d0; w < p0; w++) g_adj[run + w] = n;
        }
        if (i1 < hi) {
            int r1 = run + p0;
            g_off[i1] = r1; g_cur[i1] = r1;
            float nr = rsqrtf((float)d1 + 1.0f);
            g_norm[i1] = nr; g_xn[i1] = x[i1] * nr;
            for (int w = d1; w < p1; w++) g_adj[r1 + w] = n;
        }
    }
    gbar();

    // ---- P3: CSR fill (edge reads streaming) ----
    for (int e = gt; e < E; e += NB * NT) {
        int d = __ldcs(dst + e);
        int s = __ldcs(src + e);
        int pos = atomicAdd(&g_cur[d], 1);
        g_adj[pos] = s;
    }
    gbar();

    // ---- P4: layer-1 scalar gather (8-lane groups) + stats ----
    {
        float a = 0.f, a2 = 0.f;
        for (int node = ggrp; node < n; node += NGRP) {
            int beg = g_off[node];
            int pd = (g_deg[node] + 7) & ~7;
            float acc = 0.f;
            for (int j0 = 0; j0 < pd; j0 += 8) acc += g_xn[g_adj[beg + j0 + q]];
            acc += __shfl_xor_sync(gmask, acc, 4, 8);
            acc += __shfl_xor_sync(gmask, acc, 2, 8);
            acc += __shfl_xor_sync(gmask, acc, 1, 8);
            if (q == 0) {
                float nr = g_norm[node];
                float sv = nr * acc + x[node] * nr * nr;
                g_s[node] = sv;
                a += sv; a2 += sv * sv;
            }
        }
        a  += __shfl_xor_sync(0xffffffffu, a, 8);  a  += __shfl_xor_sync(0xffffffffu, a, 16);
        a2 += __shfl_xor_sync(0xffffffffu, a2, 8); a2 += __shfl_xor_sync(0xffffffffu, a2, 16);
        __syncthreads();
        if (lane == 0) { shd[wid] = (double)a; shd[8 + wid] = (double)a2; }
        __syncthreads();
        if (tid == 0) {
            double s1 = 0.0, s2 = 0.0;
            #pragma unroll
            for (int k = 0; k < 8; k++) { s1 += shd[k]; s2 += shd[8 + k]; }
            atomicAdd(&g_stats[0], s1); atomicAdd(&g_stats[1], s2);
        }
        __syncthreads();
    }
    gbar();

    // ---- P5: layer-1 dense -> U2h (fp16 messages) ----
    {
        for (int i = tid; i < 256; i += NT) sW4[i] = ((const float4*)W2)[i];
        __syncthreads();
        double inv = 1.0 / (double)n;
        double mu = g_stats[0] * inv;
        double vr = g_stats[1] * inv - mu * mu;
        float vrf = (float)vr, meanf = (float)mu;
        float4 w4 = ((const float4*)W1)[q];
        float4 gg = ((const float4*)g1)[q], bb = ((const float4*)be1)[q];
        float4 al;
        al.x = gg.x * w4.x * rsqrtf(vrf * w4.x * w4.x + BN_EPS);
        al.y = gg.y * w4.y * rsqrtf(vrf * w4.y * w4.y + BN_EPS);
        al.z = gg.z * w4.z * rsqrtf(vrf * w4.z * w4.z + BN_EPS);
        al.w = gg.w * w4.w * rsqrtf(vrf * w4.w * w4.w + BN_EPS);
        for (int node = ggrp; node < n; node += NGRP) {
            float sv = g_s[node];
            float4 h;
            h.x = fmaxf(al.x * (sv - meanf) + bb.x, 0.f);
            h.y = fmaxf(al.y * (sv - meanf) + bb.y, 0.f);
            h.z = fmaxf(al.z * (sv - meanf) + bb.z, 0.f);
            h.w = fmaxf(al.w * (sv - meanf) + bb.w, 0.f);
            float4 t = {0.f, 0.f, 0.f, 0.f};
            #pragma unroll
            for (int k = 0; k < 32; k++) {
                float hk = ((k & 3) == 0) ? h.x : ((k & 3) == 1) ? h.y : ((k & 3) == 2) ? h.z : h.w;
                hk = __shfl_sync(gmask, hk, k >> 2, 8);
                float4 w = sW4[k * 8 + q];
                t.x += hk * w.x; t.y += hk * w.y; t.z += hk * w.z; t.w += hk * w.w;
            }
            float nr = g_norm[node];
            float4 o; o.x = t.x * nr; o.y = t.y * nr; o.z = t.z * nr; o.w = t.w * nr;
            g_U2h[node * 8 + q] = toH(o);
        }
        __syncthreads();
    }
    gbar();

    // ---- P6: layer-2 gather: U2h -> Z (=Z2) ----
    gatherH(g_U2h, g_Z, b2, &g_stats[2], &g_stats[34], n, shd);
    gbar();

    // ---- P7: layer-2 dense: Z(Z2) -> U3h ----
    denseH(g_Z, g_U3h, g2, be2, W3, &g_stats[2], &g_stats[34], n, sW4);
    gbar();

    // ---- P8: layer-3 gather: U3h -> Z (=Z3; Z2 dead) ----
    gatherH(g_U3h, g_Z, b3, &g_stats[66], &g_stats[98], n, shd);
    gbar();

    // ---- P9: output from Z(Z3) (4 nodes/warp) ----
    {
        const double* ss = &g_stats[66];
        const double* sq = &g_stats[98];
        double inv = 1.0 / (double)n;
        float4 gl = ((const float4*)g3)[q], bl = ((const float4*)be3)[q];
        float4 fw = ((const float4*)fcW)[q];
        float fb = fcb[0];
        float4 mean, sd;
        double m0 = ss[4*q+0]*inv, m1 = ss[4*q+1]*inv, m2 = ss[4*q+2]*inv, m3 = ss[4*q+3]*inv;
        sd.x = rsqrtf((float)(sq[4*q+0]*inv - m0*m0) + BN_EPS);
        sd.y = rsqrtf((float)(sq[4*q+1]*inv - m1*m1) + BN_EPS);
        sd.z = rsqrtf((float)(sq[4*q+2]*inv - m2*m2) + BN_EPS);
        sd.w = rsqrtf((float)(sq[4*q+3]*inv - m3*m3) + BN_EPS);
        mean.x = (float)m0; mean.y = (float)m1; mean.z = (float)m2; mean.w = (float)m3;
        for (int node = ggrp; node < n; node += NGRP) {
            float4 z = g_Z[node * 8 + q];
            float4 h;
            h.x = fmaxf(gl.x * ((z.x - mean.x) * sd.x) + bl.x, 0.f);
            h.y = fmaxf(gl.y * ((z.y - mean.y) * sd.y) + bl.y, 0.f);
            h.z = fmaxf(gl.z * ((z.z - mean.z) * sd.z) + bl.z, 0.f);
            h.w = fmaxf(gl.w * ((z.w - mean.w) * sd.w) + bl.w, 0.f);
            float v = h.x * fw.x + h.y * fw.y + h.z * fw.z + h.w * fw.w;
            v += __shfl_xor_sync(gmask, v, 4, 8);
            v += __shfl_xor_sync(gmask, v, 2, 8);
            v += __shfl_xor_sync(gmask, v, 1, 8);
            if (q == 0) out[node] = v + fb;
        }
    }
}

extern "C" void kernel_launch(void* const* d_in, const int* in_sizes, int n_in,
                              void* d_out, int out_size) {
    const float* x   = (const float*)d_in[0];
    const int*   ei  = (const int*)d_in[1];     // int32 edge_index
    const float* W1  = (const float*)d_in[3];
    const float* g1  = (const float*)d_in[5];
    const float* be1 = (const float*)d_in[6];
    const float* W2  = (const float*)d_in[7];
    const float* b2  = (const float*)d_in[8];
    const float* g2  = (const float*)d_in[9];
    const float* be2 = (const float*)d_in[10];
    const float* W3  = (const float*)d_in[11];
    const float* b3  = (const float*)d_in[12];
    const float* g3  = (const float*)d_in[13];
    const float* be3 = (const float*)d_in[14];
    const float* fcW = (const float*)d_in[15];
    const float* fcb = (const float*)d_in[16];
    float* out = (float*)d_out;

    int n = in_sizes[0];
    int E = in_sizes[1] / 2;
    const int* src = ei;
    const int* dst = ei + E;

    k_mega<<<NB, NT>>>(x, src, dst, W1, g1, be1, W2, b2, g2, be2,
                       W3, b3, g3, be3, fcW, fcb, out, n, E);
}